// round 13
// baseline (speedup 1.0000x reference)
#include <cuda_runtime.h>
#include <cuda_bf16.h>
#include <math.h>

// ---------------------------------------------------------------------------
// MnistAdditionModule: LeNet (16384 digit images) -> per-digit log-softmax
//                      -> circuit over n1+n2 sums  => out [4096, 199] fp32
// Images processed in PAIRS packed into f32x2 lanes end-to-end.
// conv1+conv2 fused; fc+log_softmax+circuit fused (circuit is block-local:
// one fc block's 64 images = 16 complete batch elements).
// ---------------------------------------------------------------------------

#define N_IMAGES 16384
#define N_PAIRS  8192
#define BATCH    4096

typedef unsigned long long u64;

__device__ __forceinline__ u64 pack_dup(float v) {
    u64 r; asm("mov.b64 %0, {%1, %1};" : "=l"(r) : "f"(v)); return r;
}
__device__ __forceinline__ u64 pack2(float a, float b) {
    u64 r; asm("mov.b64 %0, {%1, %2};" : "=l"(r) : "f"(a), "f"(b)); return r;
}
__device__ __forceinline__ void fma2(u64& c, u64 a, u64 b) {
    asm("fma.rn.f32x2 %0, %1, %2, %0;" : "+l"(c) : "l"(a), "l"(b));
}
__device__ __forceinline__ float2 unpk(u64 v) {
    float2 f; asm("mov.b64 {%0, %1}, %2;" : "=f"(f.x), "=f"(f.y) : "l"(v)); return f;
}

// intermediate buffers (static device memory; pair-interleaved u64)
__device__ u64   g_out2P[N_PAIRS * 256];           // conv2 out, [pair][feature]
__device__ __align__(16) float g_w1T[256 * 120];   // fc1 weights, k-major
__device__ __align__(16) float g_w2T[120 * 84];    // fc2 weights, k-major

// ---------------------------------------------------------------------------
// K0: prep — transpose fc weights to k-major global (tiny).
// ---------------------------------------------------------------------------
__global__ void prep_kernel(const float* __restrict__ w1,
                            const float* __restrict__ w2) {
    int t = blockIdx.x * 256 + threadIdx.x;
    for (int i = t; i < 30720; i += gridDim.x * 256) {
        int j = i >> 8, k = i & 255;               // w1 is [120][256]
        g_w1T[k * 120 + j] = w1[i];
    }
    for (int i = t; i < 10080; i += gridDim.x * 256) {
        int j = i / 120, k = i - j * 120;          // w2 is [84][120]
        g_w2T[k * 84 + j] = w2[i];
    }
}

// ---------------------------------------------------------------------------
// K1: FUSED conv1+conv2 (+bias/pool/relu each). One block = 2 image pairs,
// 288 threads, ~47 KB smem (4 CTAs/SM). conv1 output planes never leave smem.
// ---------------------------------------------------------------------------
__global__ void conv_kernel(const float* __restrict__ images,
                            const float* __restrict__ w1c,
                            const float* __restrict__ b1c,
                            const float* __restrict__ w2c,
                            const float* __restrict__ b2c) {
    __shared__ u64 s_img[1568];    // 2 pairs x 784, pair-packed
    __shared__ u64 s_o1[1728];     // 2 pairs x 6 x 12 x 12 (conv1 out)
    __shared__ u64 s_w1[150];      // conv1 weights, dup'd
    __shared__ u64 s_w2[2400];     // conv2 weights, dup'd
    __shared__ float s_b1[6], s_b2[16];

    int p0 = blockIdx.x * 2;       // first pair of this block
    int t = threadIdx.x;           // 288 threads

    // fills
    for (int i = t; i < 1568; i += 288) {
        int p = (i < 784) ? 0 : 1;
        int k = i - p * 784;
        const float* imA = images + (2 * (p0 + p)) * 784;
        s_img[i] = pack2(imA[k], imA[784 + k]);
    }
    if (t < 150) s_w1[t] = pack_dup(w1c[t]);
    for (int i = t; i < 2400; i += 288) s_w2[i] = pack_dup(w2c[i]);
    if (t < 6)  s_b1[t] = b1c[t];
    if (t < 16) s_b2[t] = b2c[t];
    __syncthreads();

    // ---- Phase 1: conv1 + pool + relu -> s_o1 ----
    {
        int sub = (t >= 144) ? 1 : 0;
        int tt = t - sub * 144;
        int oh = tt / 12, ow = tt - oh * 12;
        const u64* img = s_img + sub * 784;

        u64 win[6][6];
#pragma unroll
        for (int i = 0; i < 6; i++)
#pragma unroll
            for (int j = 0; j < 6; j++)
                win[i][j] = img[(2 * oh + i) * 28 + (2 * ow + j)];

        u64* o1 = s_o1 + sub * 864 + tt;
#pragma unroll
        for (int ch = 0; ch < 6; ch++) {
            u64 a00 = 0, a01 = 0, a10 = 0, a11 = 0;
            const u64* wp = s_w1 + ch * 25;
#pragma unroll
            for (int i = 0; i < 5; i++)
#pragma unroll
                for (int j = 0; j < 5; j++) {
                    u64 wv = wp[i * 5 + j];
                    fma2(a00, win[i][j],         wv);
                    fma2(a01, win[i][j + 1],     wv);
                    fma2(a10, win[i + 1][j],     wv);
                    fma2(a11, win[i + 1][j + 1], wv);
                }
            float2 f00 = unpk(a00), f01 = unpk(a01), f10 = unpk(a10), f11 = unpk(a11);
            float bv = s_b1[ch];
            float mA = fmaxf(fmaxf(f00.x, f01.x), fmaxf(f10.x, f11.x)) + bv;
            float mB = fmaxf(fmaxf(f00.y, f01.y), fmaxf(f10.y, f11.y)) + bv;
            o1[ch * 144] = pack2(fmaxf(mA, 0.f), fmaxf(mB, 0.f));
        }
    }
    __syncthreads();

    // ---- Phase 2: conv2 + pool + relu -> g_out2P ----
    if (t < 256) {
        int pairIdx = t >> 7, local = t & 127;
        int chp = local >> 4, pos = local & 15;   // chp: channel pair 0..7
        int oh = pos >> 2, ow = pos & 3;
        const u64* inp = s_o1 + pairIdx * 864;

        u64 acc[2][4] = {};        // [ch-in-pair][a00,a01,a10,a11]
        for (int ic = 0; ic < 6; ic++) {
            u64 win[6][6];
#pragma unroll
            for (int i = 0; i < 6; i++)
#pragma unroll
                for (int j = 0; j < 6; j++)
                    win[i][j] = inp[ic * 144 + (2 * oh + i) * 12 + (2 * ow + j)];
#pragma unroll
            for (int c = 0; c < 2; c++) {
                int ch = chp * 2 + c;
                const u64* wp = s_w2 + (ch * 6 + ic) * 25;
#pragma unroll
                for (int i = 0; i < 5; i++)
#pragma unroll
                    for (int j = 0; j < 5; j++) {
                        u64 wv = wp[i * 5 + j];
                        fma2(acc[c][0], win[i][j],         wv);
                        fma2(acc[c][1], win[i][j + 1],     wv);
                        fma2(acc[c][2], win[i + 1][j],     wv);
                        fma2(acc[c][3], win[i + 1][j + 1], wv);
                    }
            }
        }
        u64* out = g_out2P + (p0 + pairIdx) * 256;
#pragma unroll
        for (int c = 0; c < 2; c++) {
            int ch = chp * 2 + c;
            float2 f0 = unpk(acc[c][0]), f1 = unpk(acc[c][1]);
            float2 f2 = unpk(acc[c][2]), f3 = unpk(acc[c][3]);
            float bv = s_b2[ch];
            float mA = fmaxf(fmaxf(f0.x, f1.x), fmaxf(f2.x, f3.x)) + bv;
            float mB = fmaxf(fmaxf(f0.y, f1.y), fmaxf(f2.y, f3.y)) + bv;
            out[ch * 16 + pos] = pack2(fmaxf(mA, 0.f), fmaxf(mB, 0.f));
        }
    }
}

// ---------------------------------------------------------------------------
// K3: fc stack (R11 config: 64 img/block, 256 blocks, ~106 KB smem, 2 CTA/SM,
// weight+x prefetch) + FUSED log_softmax + circuit. A block's 64 images are
// exactly 16 batch elements, so the circuit is block-local: p1/p2 tables live
// in the dead s_h1 region, outputs go straight to d_out. g_lp eliminated.
// ---------------------------------------------------------------------------
#define FC_X2_U64   (256 * 33)
#define FC_H1_U64   (120 * 33)
#define FC_TAIL_F   (840 + 120 + 84 + 16 + 640 + 64)
#define FC_SMEM_BYTES (FC_X2_U64 * 8 + FC_H1_U64 * 8 + FC_TAIL_F * 4)

__global__ void __launch_bounds__(256, 2)
fc_kernel(const float* __restrict__ b1,
          const float* __restrict__ b2,
          const float* __restrict__ w3, const float* __restrict__ b3,
          float* __restrict__ gout) {
    extern __shared__ __align__(16) char smraw[];
    u64*   s_x2 = (u64*)smraw;                 // [256][33] image-pair acts
    u64*   s_h1 = s_x2 + FC_X2_U64;            // [120][33]; circuit p-tables later
    u64*   s_h2 = s_x2;                        // [84][33], aliases dead x
    float* s_w3 = (float*)(s_h1 + FC_H1_U64);  // [84][10] k-major
    float* s_b1 = s_w3 + 840;                  // 120
    float* s_b2 = s_b1 + 120;                  // 84
    float* s_b3 = s_b2 + 84;                   // 16
    float* s_z  = s_b3 + 16;                   // [64][10] logits -> lp in place
    float* s_mx = s_z + 640;                   // [64] per-image max lp

    int t = threadIdx.x;                       // 256 threads
    int pb = blockIdx.x * 32;                  // base pair

    // fill x2 straight from pair-packed conv2 output (coalesced u64 rows)
    for (int idx = t; idx < 32 * 256; idx += 256) {
        int p = idx >> 8, k = idx & 255;
        s_x2[k * 33 + p] = g_out2P[(pb + p) * 256 + k];
    }
    for (int i = t; i < 840; i += 256) {
        int j = i / 84, k = i - j * 84;
        s_w3[k * 10 + j] = w3[i];
    }
    if (t < 120) s_b1[t] = b1[t];
    if (t < 84)  s_b2[t] = b2[t];
    if (t < 16)  s_b3[t] = (t < 10) ? b3[t] : 0.f;
    __syncthreads();

    int w = t >> 5, jj = t & 31;
    int pg = w * 4;                            // this warp's 4 image pairs

    // fc1: 8 images (4 pairs) x 4 outputs (j-quad); jj < 30. Prefetched.
    if (jj < 30) {
        u64 acc[4][4];
#pragma unroll
        for (int u = 0; u < 4; u++) {
            u64 bv = pack_dup(s_b1[4 * jj + u]);
            acc[0][u] = bv; acc[1][u] = bv; acc[2][u] = bv; acc[3][u] = bv;
        }
        const float* wbase = g_w1T + 4 * jj;
        const u64*   xbase = s_x2 + pg;
        float4 wq = *(const float4*)(wbase);
        u64 x0 = xbase[0], x1 = xbase[1], x2 = xbase[2], x3 = xbase[3];
#pragma unroll 4
        for (int k = 0; k < 256; k++) {
            float4 wc = wq;
            u64 c0 = x0, c1 = x1, c2 = x2, c3 = x3;
            if (k < 255) {
                wq = *(const float4*)(wbase + (k + 1) * 120);
                const u64* xn = xbase + (k + 1) * 33;
                x0 = xn[0]; x1 = xn[1]; x2 = xn[2]; x3 = xn[3];
            }
            u64 w0 = pack_dup(wc.x), w1 = pack_dup(wc.y);
            u64 w2 = pack_dup(wc.z), w3v = pack_dup(wc.w);
            fma2(acc[0][0], c0, w0);  fma2(acc[1][0], c1, w0);
            fma2(acc[2][0], c2, w0);  fma2(acc[3][0], c3, w0);
            fma2(acc[0][1], c0, w1);  fma2(acc[1][1], c1, w1);
            fma2(acc[2][1], c2, w1);  fma2(acc[3][1], c3, w1);
            fma2(acc[0][2], c0, w2);  fma2(acc[1][2], c1, w2);
            fma2(acc[2][2], c2, w2);  fma2(acc[3][2], c3, w2);
            fma2(acc[0][3], c0, w3v); fma2(acc[1][3], c1, w3v);
            fma2(acc[2][3], c2, w3v); fma2(acc[3][3], c3, w3v);
        }
#pragma unroll
        for (int i = 0; i < 4; i++)
#pragma unroll
            for (int u = 0; u < 4; u++) {
                float2 f = unpk(acc[i][u]);
                s_h1[(4 * jj + u) * 33 + pg + i] =
                    pack2(fmaxf(f.x, 0.f), fmaxf(f.y, 0.f));
            }
    }
    __syncthreads();

    // fc2: 8 images x 4 outputs (j-quad); jj < 21. Prefetched.
    if (jj < 21) {
        u64 acc[4][4];
#pragma unroll
        for (int u = 0; u < 4; u++) {
            u64 bv = pack_dup(s_b2[4 * jj + u]);
            acc[0][u] = bv; acc[1][u] = bv; acc[2][u] = bv; acc[3][u] = bv;
        }
        const float* wbase = g_w2T + 4 * jj;
        const u64*   xbase = s_h1 + pg;
        float4 wq = *(const float4*)(wbase);
        u64 x0 = xbase[0], x1 = xbase[1], x2 = xbase[2], x3 = xbase[3];
#pragma unroll 4
        for (int k = 0; k < 120; k++) {
            float4 wc = wq;
            u64 c0 = x0, c1 = x1, c2 = x2, c3 = x3;
            if (k < 119) {
                wq = *(const float4*)(wbase + (k + 1) * 84);
                const u64* xn = xbase + (k + 1) * 33;
                x0 = xn[0]; x1 = xn[1]; x2 = xn[2]; x3 = xn[3];
            }
            u64 w0 = pack_dup(wc.x), w1 = pack_dup(wc.y);
            u64 w2 = pack_dup(wc.z), w3v = pack_dup(wc.w);
            fma2(acc[0][0], c0, w0);  fma2(acc[1][0], c1, w0);
            fma2(acc[2][0], c2, w0);  fma2(acc[3][0], c3, w0);
            fma2(acc[0][1], c0, w1);  fma2(acc[1][1], c1, w1);
            fma2(acc[2][1], c2, w1);  fma2(acc[3][1], c3, w1);
            fma2(acc[0][2], c0, w2);  fma2(acc[1][2], c1, w2);
            fma2(acc[2][2], c2, w2);  fma2(acc[3][2], c3, w2);
            fma2(acc[0][3], c0, w3v); fma2(acc[1][3], c1, w3v);
            fma2(acc[2][3], c2, w3v); fma2(acc[3][3], c3, w3v);
        }
#pragma unroll
        for (int i = 0; i < 4; i++)
#pragma unroll
            for (int u = 0; u < 4; u++) {
                float2 f = unpk(acc[i][u]);
                s_h2[(4 * jj + u) * 33 + pg + i] =
                    pack2(fmaxf(f.x, 0.f), fmaxf(f.y, 0.f));
            }
    }
    __syncthreads();

    // fc3: 64 img x 10 outputs = 640 dots over 84 (tiny)
    const float* h2f = (const float*)s_h2;
    for (int o = t; o < 640; o += 256) {
        int g = o / 10, j = o - g * 10;
        int p = g >> 1, lane = g & 1;
        float acc = s_b3[j];
#pragma unroll
        for (int k = 0; k < 84; k++)
            acc = fmaf(h2f[(k * 33 + p) * 2 + lane], s_w3[k * 10 + j], acc);
        s_z[g * 10 + j] = acc;
    }
    __syncthreads();

    // log_softmax per image, in place; record per-image max log-prob (m - lse)
    if (t < 64) {
        float* z = s_z + t * 10;
        float m = -1e30f;
#pragma unroll
        for (int i = 0; i < 10; i++) m = fmaxf(m, z[i]);
        float s = 0.f;
#pragma unroll
        for (int i = 0; i < 10; i++) s += __expf(z[i] - m);
        float lse = __logf(s) + m;
#pragma unroll
        for (int i = 0; i < 10; i++) z[i] -= lse;
        s_mx[t] = m - lse;
    }
    __syncthreads();

    // circuit: 16 batch elements (local be uses local images 4be..4be+3).
    // p-tables alias dead s_h1: cp[be*256 + 0..99] = p1, +128..227 = p2.
    float* cp = (float*)s_h1;
    for (int idx = t; idx < 3200; idx += 256) {
        int be = idx / 200, k = idx - be * 200;
        const float* lp = s_z + be * 40;
        if (k < 100) {
            float ms = s_mx[4 * be] + s_mx[4 * be + 1];
            cp[be * 256 + k] = __expf(lp[k / 10] + lp[10 + k % 10] - ms);
        } else {
            int kk = k - 100;
            float ms = s_mx[4 * be + 2] + s_mx[4 * be + 3];
            cp[be * 256 + 128 + kk] =
                __expf(lp[20 + kk / 10] + lp[30 + kk % 10] - ms);
        }
    }
    __syncthreads();

    // outputs: 16 threads per batch element, ~12-13 sums each
    {
        int be = t >> 4, l16 = t & 15;
        float msum = s_mx[4 * be] + s_mx[4 * be + 1]
                   + s_mx[4 * be + 2] + s_mx[4 * be + 3];
        const float* p1 = cp + be * 256;
        const float* p2 = p1 + 128;
        float* ob = gout + (blockIdx.x * 16 + be) * 199;
        for (int s = l16; s < 199; s += 16) {
            int lo = max(0, s - 99), hi = min(99, s);
            float acc = 0.f;
            for (int i = lo; i <= hi; i++) acc = fmaf(p1[i], p2[s - i], acc);
            ob[s] = __logf(acc) + msum;
        }
    }
}

// ---------------------------------------------------------------------------
extern "C" void kernel_launch(void* const* d_in, const int* in_sizes, int n_in,
                              void* d_out, int out_size) {
    const float* images = (const float*)d_in[0];
    const float* c1w    = (const float*)d_in[1];
    const float* c1b    = (const float*)d_in[2];
    const float* c2w    = (const float*)d_in[3];
    const float* c2b    = (const float*)d_in[4];
    const float* f1w    = (const float*)d_in[5];
    const float* f1b    = (const float*)d_in[6];
    const float* f2w    = (const float*)d_in[7];
    const float* f2b    = (const float*)d_in[8];
    const float* f3w    = (const float*)d_in[9];
    const float* f3b    = (const float*)d_in[10];
    float* out = (float*)d_out;

    cudaFuncSetAttribute(fc_kernel, cudaFuncAttributeMaxDynamicSharedMemorySize,
                         FC_SMEM_BYTES);

    prep_kernel<<<30, 256>>>(f1w, f2w);
    conv_kernel<<<N_PAIRS / 2, 288>>>(images, c1w, c1b, c2w, c2b);
    fc_kernel<<<N_IMAGES / 64, 256, FC_SMEM_BYTES>>>(f1b, f2b, f3w, f3b, out);
}

// round 14
// speedup vs baseline: 1.0563x; 1.0563x over previous
#include <cuda_runtime.h>
#include <cuda_bf16.h>
#include <math.h>

// ---------------------------------------------------------------------------
// MnistAdditionModule: LeNet (16384 digit images) -> per-digit log-softmax
//                      -> circuit over n1+n2 sums  => out [4096, 199] fp32
// Images processed in PAIRS packed into f32x2 lanes end-to-end.
// conv1+conv2 fused in one kernel (intermediate planes stay in smem);
// fc-weight transposes folded into the conv kernel (no prep launch).
// ---------------------------------------------------------------------------

#define N_IMAGES 16384
#define N_PAIRS  8192
#define BATCH    4096

typedef unsigned long long u64;

__device__ __forceinline__ u64 pack_dup(float v) {
    u64 r; asm("mov.b64 %0, {%1, %1};" : "=l"(r) : "f"(v)); return r;
}
__device__ __forceinline__ u64 pack2(float a, float b) {
    u64 r; asm("mov.b64 %0, {%1, %2};" : "=l"(r) : "f"(a), "f"(b)); return r;
}
__device__ __forceinline__ void fma2(u64& c, u64 a, u64 b) {
    asm("fma.rn.f32x2 %0, %1, %2, %0;" : "+l"(c) : "l"(a), "l"(b));
}
__device__ __forceinline__ float2 unpk(u64 v) {
    float2 f; asm("mov.b64 {%0, %1}, %2;" : "=f"(f.x), "=f"(f.y) : "l"(v)); return f;
}

// intermediate buffers (static device memory; pair-interleaved u64)
__device__ u64   g_out2P[N_PAIRS * 256];           // conv2 out, [pair][feature]
__device__ float g_lp  [N_IMAGES * 10];            // per-image log-probs
__device__ __align__(16) float g_w1T[256 * 120];   // fc1 weights, k-major
__device__ __align__(16) float g_w2T[120 * 84];    // fc2 weights, k-major

// ---------------------------------------------------------------------------
// K1: FUSED conv1+conv2 (+bias/pool/relu each). One block = 2 image pairs,
// 288 threads, ~47 KB smem (4 CTAs/SM). conv1 output planes never leave smem.
// Blocks 0..63 additionally transpose the fc weights to k-major global
// (~640 elements each) — replaces the former prep_kernel launch.
// ---------------------------------------------------------------------------
__global__ void conv_kernel(const float* __restrict__ images,
                            const float* __restrict__ w1c,
                            const float* __restrict__ b1c,
                            const float* __restrict__ w2c,
                            const float* __restrict__ b2c,
                            const float* __restrict__ f1w,
                            const float* __restrict__ f2w) {
    __shared__ u64 s_img[1568];    // 2 pairs x 784, pair-packed
    __shared__ u64 s_o1[1728];     // 2 pairs x 6 x 12 x 12 (conv1 out)
    __shared__ u64 s_w1[150];      // conv1 weights, dup'd
    __shared__ u64 s_w2[2400];     // conv2 weights, dup'd
    __shared__ float s_b1[6], s_b2[16];

    int p0 = blockIdx.x * 2;       // first pair of this block
    int t = threadIdx.x;           // 288 threads

    // folded prep: blocks 0..63 transpose fc weights (visible before fc launch)
    if (blockIdx.x < 64) {
        int base = blockIdx.x * 480;                 // 64 * 480 = 30720
        for (int i = base + t; i < base + 480; i += 288)
            if (i < 30720) {
                int j = i >> 8, k = i & 255;         // w1 is [120][256]
                g_w1T[k * 120 + j] = f1w[i];
            }
        int base2 = blockIdx.x * 158;                // 64 * 158 >= 10080
        for (int i = base2 + t; i < base2 + 158; i += 288)
            if (i < 10080) {
                int j = i / 120, k = i - j * 120;    // w2 is [84][120]
                g_w2T[k * 84 + j] = f2w[i];
            }
    }

    // fills
    for (int i = t; i < 1568; i += 288) {
        int p = (i < 784) ? 0 : 1;
        int k = i - p * 784;
        const float* imA = images + (2 * (p0 + p)) * 784;
        s_img[i] = pack2(imA[k], imA[784 + k]);
    }
    if (t < 150) s_w1[t] = pack_dup(w1c[t]);
    for (int i = t; i < 2400; i += 288) s_w2[i] = pack_dup(w2c[i]);
    if (t < 6)  s_b1[t] = b1c[t];
    if (t < 16) s_b2[t] = b2c[t];
    __syncthreads();

    // ---- Phase 1: conv1 + pool + relu -> s_o1 ----
    {
        int sub = (t >= 144) ? 1 : 0;
        int tt = t - sub * 144;
        int oh = tt / 12, ow = tt - oh * 12;
        const u64* img = s_img + sub * 784;

        u64 win[6][6];
#pragma unroll
        for (int i = 0; i < 6; i++)
#pragma unroll
            for (int j = 0; j < 6; j++)
                win[i][j] = img[(2 * oh + i) * 28 + (2 * ow + j)];

        u64* o1 = s_o1 + sub * 864 + tt;
#pragma unroll
        for (int ch = 0; ch < 6; ch++) {
            u64 a00 = 0, a01 = 0, a10 = 0, a11 = 0;
            const u64* wp = s_w1 + ch * 25;
#pragma unroll
            for (int i = 0; i < 5; i++)
#pragma unroll
                for (int j = 0; j < 5; j++) {
                    u64 wv = wp[i * 5 + j];
                    fma2(a00, win[i][j],         wv);
                    fma2(a01, win[i][j + 1],     wv);
                    fma2(a10, win[i + 1][j],     wv);
                    fma2(a11, win[i + 1][j + 1], wv);
                }
            float2 f00 = unpk(a00), f01 = unpk(a01), f10 = unpk(a10), f11 = unpk(a11);
            float bv = s_b1[ch];
            float mA = fmaxf(fmaxf(f00.x, f01.x), fmaxf(f10.x, f11.x)) + bv;
            float mB = fmaxf(fmaxf(f00.y, f01.y), fmaxf(f10.y, f11.y)) + bv;
            o1[ch * 144] = pack2(fmaxf(mA, 0.f), fmaxf(mB, 0.f));
        }
    }
    __syncthreads();

    // ---- Phase 2: conv2 + pool + relu -> g_out2P ----
    if (t < 256) {
        int pairIdx = t >> 7, local = t & 127;
        int chp = local >> 4, pos = local & 15;   // chp: channel pair 0..7
        int oh = pos >> 2, ow = pos & 3;
        const u64* inp = s_o1 + pairIdx * 864;

        u64 acc[2][4] = {};        // [ch-in-pair][a00,a01,a10,a11]
        for (int ic = 0; ic < 6; ic++) {
            u64 win[6][6];
#pragma unroll
            for (int i = 0; i < 6; i++)
#pragma unroll
                for (int j = 0; j < 6; j++)
                    win[i][j] = inp[ic * 144 + (2 * oh + i) * 12 + (2 * ow + j)];
#pragma unroll
            for (int c = 0; c < 2; c++) {
                int ch = chp * 2 + c;
                const u64* wp = s_w2 + (ch * 6 + ic) * 25;
#pragma unroll
                for (int i = 0; i < 5; i++)
#pragma unroll
                    for (int j = 0; j < 5; j++) {
                        u64 wv = wp[i * 5 + j];
                        fma2(acc[c][0], win[i][j],         wv);
                        fma2(acc[c][1], win[i][j + 1],     wv);
                        fma2(acc[c][2], win[i + 1][j],     wv);
                        fma2(acc[c][3], win[i + 1][j + 1], wv);
                    }
            }
        }
        u64* out = g_out2P + (p0 + pairIdx) * 256;
#pragma unroll
        for (int c = 0; c < 2; c++) {
            int ch = chp * 2 + c;
            float2 f0 = unpk(acc[c][0]), f1 = unpk(acc[c][1]);
            float2 f2 = unpk(acc[c][2]), f3 = unpk(acc[c][3]);
            float bv = s_b2[ch];
            float mA = fmaxf(fmaxf(f0.x, f1.x), fmaxf(f2.x, f3.x)) + bv;
            float mB = fmaxf(fmaxf(f0.y, f1.y), fmaxf(f2.y, f3.y)) + bv;
            out[ch * 16 + pos] = pack2(fmaxf(mA, 0.f), fmaxf(mB, 0.f));
        }
    }
}

// ---------------------------------------------------------------------------
// K3: fc stack (R11 config: 64 img/block, 256 blocks, ~106 KB smem, 2 CTA/SM,
// weight+x software prefetch).
// ---------------------------------------------------------------------------
#define FC_X2_U64   (256 * 33)
#define FC_H1_U64   (120 * 33)
#define FC_TAIL_F   (840 + 120 + 84 + 16 + 640)
#define FC_SMEM_BYTES (FC_X2_U64 * 8 + FC_H1_U64 * 8 + FC_TAIL_F * 4)

__global__ void __launch_bounds__(256, 2)
fc_kernel(const float* __restrict__ b1,
          const float* __restrict__ b2,
          const float* __restrict__ w3, const float* __restrict__ b3) {
    extern __shared__ __align__(16) char smraw[];
    u64*   s_x2 = (u64*)smraw;                 // [256][33] image-pair acts
    u64*   s_h1 = s_x2 + FC_X2_U64;            // [120][33]
    u64*   s_h2 = s_x2;                        // [84][33], aliases dead x
    float* s_w3 = (float*)(s_h1 + FC_H1_U64);  // [84][10] k-major
    float* s_b1 = s_w3 + 840;                  // 120
    float* s_b2 = s_b1 + 120;                  // 84
    float* s_b3 = s_b2 + 84;                   // 16
    float* s_z  = s_b3 + 16;                   // [64][10]

    int t = threadIdx.x;                       // 256 threads
    int n0 = blockIdx.x * 64;
    int pb = blockIdx.x * 32;                  // base pair

    // fill x2 straight from pair-packed conv2 output (coalesced u64 rows)
    for (int idx = t; idx < 32 * 256; idx += 256) {
        int p = idx >> 8, k = idx & 255;
        s_x2[k * 33 + p] = g_out2P[(pb + p) * 256 + k];
    }
    for (int i = t; i < 840; i += 256) {
        int j = i / 84, k = i - j * 84;
        s_w3[k * 10 + j] = w3[i];
    }
    if (t < 120) s_b1[t] = b1[t];
    if (t < 84)  s_b2[t] = b2[t];
    if (t < 16)  s_b3[t] = (t < 10) ? b3[t] : 0.f;
    __syncthreads();

    int w = t >> 5, jj = t & 31;
    int pg = w * 4;                            // this warp's 4 image pairs

    // fc1: 8 images (4 pairs) x 4 outputs (j-quad); jj < 30. Prefetched.
    if (jj < 30) {
        u64 acc[4][4];
#pragma unroll
        for (int u = 0; u < 4; u++) {
            u64 bv = pack_dup(s_b1[4 * jj + u]);
            acc[0][u] = bv; acc[1][u] = bv; acc[2][u] = bv; acc[3][u] = bv;
        }
        const float* wbase = g_w1T + 4 * jj;
        const u64*   xbase = s_x2 + pg;
        float4 wq = *(const float4*)(wbase);
        u64 x0 = xbase[0], x1 = xbase[1], x2 = xbase[2], x3 = xbase[3];
#pragma unroll 4
        for (int k = 0; k < 256; k++) {
            float4 wc = wq;
            u64 c0 = x0, c1 = x1, c2 = x2, c3 = x3;
            if (k < 255) {
                wq = *(const float4*)(wbase + (k + 1) * 120);
                const u64* xn = xbase + (k + 1) * 33;
                x0 = xn[0]; x1 = xn[1]; x2 = xn[2]; x3 = xn[3];
            }
            u64 w0 = pack_dup(wc.x), w1 = pack_dup(wc.y);
            u64 w2 = pack_dup(wc.z), w3v = pack_dup(wc.w);
            fma2(acc[0][0], c0, w0);  fma2(acc[1][0], c1, w0);
            fma2(acc[2][0], c2, w0);  fma2(acc[3][0], c3, w0);
            fma2(acc[0][1], c0, w1);  fma2(acc[1][1], c1, w1);
            fma2(acc[2][1], c2, w1);  fma2(acc[3][1], c3, w1);
            fma2(acc[0][2], c0, w2);  fma2(acc[1][2], c1, w2);
            fma2(acc[2][2], c2, w2);  fma2(acc[3][2], c3, w2);
            fma2(acc[0][3], c0, w3v); fma2(acc[1][3], c1, w3v);
            fma2(acc[2][3], c2, w3v); fma2(acc[3][3], c3, w3v);
        }
#pragma unroll
        for (int i = 0; i < 4; i++)
#pragma unroll
            for (int u = 0; u < 4; u++) {
                float2 f = unpk(acc[i][u]);
                s_h1[(4 * jj + u) * 33 + pg + i] =
                    pack2(fmaxf(f.x, 0.f), fmaxf(f.y, 0.f));
            }
    }
    __syncthreads();

    // fc2: 8 images x 4 outputs (j-quad); jj < 21. Prefetched.
    if (jj < 21) {
        u64 acc[4][4];
#pragma unroll
        for (int u = 0; u < 4; u++) {
            u64 bv = pack_dup(s_b2[4 * jj + u]);
            acc[0][u] = bv; acc[1][u] = bv; acc[2][u] = bv; acc[3][u] = bv;
        }
        const float* wbase = g_w2T + 4 * jj;
        const u64*   xbase = s_h1 + pg;
        float4 wq = *(const float4*)(wbase);
        u64 x0 = xbase[0], x1 = xbase[1], x2 = xbase[2], x3 = xbase[3];
#pragma unroll 4
        for (int k = 0; k < 120; k++) {
            float4 wc = wq;
            u64 c0 = x0, c1 = x1, c2 = x2, c3 = x3;
            if (k < 119) {
                wq = *(const float4*)(wbase + (k + 1) * 84);
                const u64* xn = xbase + (k + 1) * 33;
                x0 = xn[0]; x1 = xn[1]; x2 = xn[2]; x3 = xn[3];
            }
            u64 w0 = pack_dup(wc.x), w1 = pack_dup(wc.y);
            u64 w2 = pack_dup(wc.z), w3v = pack_dup(wc.w);
            fma2(acc[0][0], c0, w0);  fma2(acc[1][0], c1, w0);
            fma2(acc[2][0], c2, w0);  fma2(acc[3][0], c3, w0);
            fma2(acc[0][1], c0, w1);  fma2(acc[1][1], c1, w1);
            fma2(acc[2][1], c2, w1);  fma2(acc[3][1], c3, w1);
            fma2(acc[0][2], c0, w2);  fma2(acc[1][2], c1, w2);
            fma2(acc[2][2], c2, w2);  fma2(acc[3][2], c3, w2);
            fma2(acc[0][3], c0, w3v); fma2(acc[1][3], c1, w3v);
            fma2(acc[2][3], c2, w3v); fma2(acc[3][3], c3, w3v);
        }
#pragma unroll
        for (int i = 0; i < 4; i++)
#pragma unroll
            for (int u = 0; u < 4; u++) {
                float2 f = unpk(acc[i][u]);
                s_h2[(4 * jj + u) * 33 + pg + i] =
                    pack2(fmaxf(f.x, 0.f), fmaxf(f.y, 0.f));
            }
    }
    __syncthreads();

    // fc3: 64 img x 10 outputs = 640 dots over 84 (tiny)
    const float* h2f = (const float*)s_h2;
    for (int o = t; o < 640; o += 256) {
        int g = o / 10, j = o - g * 10;
        int p = g >> 1, lane = g & 1;
        float acc = s_b3[j];
#pragma unroll
        for (int k = 0; k < 84; k++)
            acc = fmaf(h2f[(k * 33 + p) * 2 + lane], s_w3[k * 10 + j], acc);
        s_z[g * 10 + j] = acc;
    }
    __syncthreads();

    // log_softmax per image
    if (t < 64) {
        const float* z = s_z + t * 10;
        float m = -1e30f;
#pragma unroll
        for (int i = 0; i < 10; i++) m = fmaxf(m, z[i]);
        float s = 0.f;
#pragma unroll
        for (int i = 0; i < 10; i++) s += __expf(z[i] - m);
        float lse = __logf(s) + m;
        float* out = g_lp + (n0 + t) * 10;
#pragma unroll
        for (int i = 0; i < 10; i++) out[i] = z[i] - lse;
    }
}

// ---------------------------------------------------------------------------
// K4: circuit (standalone, R5/R11 version).
// out[s] = log(sum_i p1[i]*p2[s-i]) + m1 + m2.
// ---------------------------------------------------------------------------
__global__ void circuit_kernel(float* __restrict__ out) {
    __shared__ float p1[100], p2[100];
    __shared__ float msum[2];
    int b = blockIdx.x;
    const float* lp = g_lp + b * 40;
    int t = threadIdx.x;   // 256 threads

    if (t == 0) {
        float m0 = -1e30f, m1 = -1e30f, m2 = -1e30f, m3 = -1e30f;
#pragma unroll
        for (int i = 0; i < 10; i++) {
            m0 = fmaxf(m0, lp[i]);
            m1 = fmaxf(m1, lp[10 + i]);
            m2 = fmaxf(m2, lp[20 + i]);
            m3 = fmaxf(m3, lp[30 + i]);
        }
        msum[0] = m0 + m1;
        msum[1] = m2 + m3;
    }
    __syncthreads();
    if (t < 100) {
        p1[t] = __expf(lp[t / 10] + lp[10 + t % 10] - msum[0]);
    } else if (t < 200) {
        int k = t - 100;
        p2[k] = __expf(lp[20 + k / 10] + lp[30 + k % 10] - msum[1]);
    }
    __syncthreads();
    if (t < 199) {
        int lo = max(0, t - 99), hi = min(99, t);
        float s = 0.f;
        for (int i = lo; i <= hi; i++) s = fmaf(p1[i], p2[t - i], s);
        out[b * 199 + t] = __logf(s) + msum[0] + msum[1];
    }
}

// ---------------------------------------------------------------------------
extern "C" void kernel_launch(void* const* d_in, const int* in_sizes, int n_in,
                              void* d_out, int out_size) {
    const float* images = (const float*)d_in[0];
    const float* c1w    = (const float*)d_in[1];
    const float* c1b    = (const float*)d_in[2];
    const float* c2w    = (const float*)d_in[3];
    const float* c2b    = (const float*)d_in[4];
    const float* f1w    = (const float*)d_in[5];
    const float* f1b    = (const float*)d_in[6];
    const float* f2w    = (const float*)d_in[7];
    const float* f2b    = (const float*)d_in[8];
    const float* f3w    = (const float*)d_in[9];
    const float* f3b    = (const float*)d_in[10];
    float* out = (float*)d_out;

    cudaFuncSetAttribute(fc_kernel, cudaFuncAttributeMaxDynamicSharedMemorySize,
                         FC_SMEM_BYTES);

    conv_kernel<<<N_PAIRS / 2, 288>>>(images, c1w, c1b, c2w, c2b, f1w, f2w);
    fc_kernel<<<N_IMAGES / 64, 256, FC_SMEM_BYTES>>>(f1b, f2b, f3w, f3b);
    circuit_kernel<<<BATCH, 256>>>(out);
}